// round 6
// baseline (speedup 1.0000x reference)
#include <cuda_runtime.h>

#define NATOMS 1024
#define NBATCH 32
#define TPB    256
#define CHUNKS 4                 // i-chunks per batch (256 atoms each)
#define JSPLIT 8                 // j-eighths per i-chunk
#define JTILE  (NATOMS / JSPLIT) // 128
#define JPAIRS (JTILE / 2)       // 64 packed pairs
// grid = NBATCH * CHUNKS * JSPLIT = 1024 blocks

typedef unsigned long long ull;

__device__ float4 d_mean[NBATCH];  // per-batch position mean (scratch)

__device__ __forceinline__ ull f2pack(float lo, float hi) {
    ull r;
    asm("mov.b64 %0, {%1, %2};" : "=l"(r)
        : "r"(__float_as_uint(lo)), "r"(__float_as_uint(hi)));
    return r;
}
__device__ __forceinline__ void f2unpack(ull v, float& lo, float& hi) {
    unsigned a, b;
    asm("mov.b64 {%0, %1}, %2;" : "=r"(a), "=r"(b) : "l"(v));
    lo = __uint_as_float(a);
    hi = __uint_as_float(b);
}
__device__ __forceinline__ ull f2add(ull a, ull b) {
    ull r; asm("add.rn.f32x2 %0, %1, %2;" : "=l"(r) : "l"(a), "l"(b)); return r;
}
__device__ __forceinline__ ull f2mul(ull a, ull b) {
    ull r; asm("mul.rn.f32x2 %0, %1, %2;" : "=l"(r) : "l"(a), "l"(b)); return r;
}
__device__ __forceinline__ ull f2fma(ull a, ull b, ull c) {
    ull r; asm("fma.rn.f32x2 %0, %1, %2, %3;" : "=l"(r) : "l"(a), "l"(b), "l"(c)); return r;
}

// Pre-pass: zero the output AND compute per-batch means (block b -> batch b).
__global__ __launch_bounds__(TPB) void lj_pre(const float* __restrict__ pos,
                                              float* __restrict__ out, int n) {
    __shared__ float wred[8 * 3];
    const int tid  = threadIdx.x;
    const int b    = blockIdx.x;
    const int lane = tid & 31;
    const int warp = tid >> 5;

    // zero output (grid-stride over all 32*256 threads)
    for (int idx = b * TPB + tid; idx < n; idx += NBATCH * TPB) out[idx] = 0.0f;

    // mean of batch b
    const float* __restrict__ p = pos + (size_t)b * NATOMS * 3;
    float mx = 0.0f, my = 0.0f, mz = 0.0f;
    for (int a = tid; a < NATOMS; a += TPB) {
        mx += p[3 * a + 0];
        my += p[3 * a + 1];
        mz += p[3 * a + 2];
    }
    #pragma unroll
    for (int o = 16; o > 0; o >>= 1) {
        mx += __shfl_xor_sync(0xFFFFFFFFu, mx, o);
        my += __shfl_xor_sync(0xFFFFFFFFu, my, o);
        mz += __shfl_xor_sync(0xFFFFFFFFu, mz, o);
    }
    if (lane == 0) {
        wred[warp * 3 + 0] = mx;
        wred[warp * 3 + 1] = my;
        wred[warp * 3 + 2] = mz;
    }
    __syncthreads();
    if (tid == 0) {
        mx = 0.0f; my = 0.0f; mz = 0.0f;
        #pragma unroll
        for (int k = 0; k < 8; k++) {
            mx += wred[k * 3 + 0];
            my += wred[k * 3 + 1];
            mz += wred[k * 3 + 2];
        }
        const float inv_n = 1.0f / (float)NATOMS;
        d_mean[b] = make_float4(mx * inv_n, my * inv_n, mz * inv_n, 0.0f);
    }
}

// Inner pair loop. Tile pre-packed: sxy[m] = {(-x0,-x1),(-y0,-y1)}, szz[m] = (-z0,-z1).
template <bool SELF>
__device__ __forceinline__ void pair_loop(
    const ulonglong2* __restrict__ sxy, const ull* __restrict__ szz,
    ull xi2, ull yi2, ull zi2, int m0, int m1,
    ull& fx2, ull& fy2, ull& fz2, ull& a6, ull& a12)
{
    const ull MINUS1 = f2pack(-1.0f, -1.0f);
    #pragma unroll 8
    for (int m = 0; m < JPAIRS; m++) {
        ulonglong2 q = sxy[m];              // LDS.128
        ull nz2 = szz[m];                   // LDS.64

        ull dx2 = f2add(xi2, q.x);
        ull dy2 = f2add(yi2, q.y);
        ull dz2 = f2add(zi2, nz2);
        ull sq2 = f2mul(dx2, dx2);
        sq2 = f2fma(dy2, dy2, sq2);
        sq2 = f2fma(dz2, dz2, sq2);

        float s0, s1;
        f2unpack(sq2, s0, s1);
        if (SELF) {                         // self-pair -> rcp underflows to 0
            s0 = (m == m0) ? 3.0e38f : s0;
            s1 = (m == m1) ? 3.0e38f : s1;
        }
        float r0 = __fdividef(1.0f, s0);    // MUFU.RCP
        float r1 = __fdividef(1.0f, s1);
        ull invsq2 = f2pack(r0, r1);

        ull t4    = f2mul(invsq2, invsq2);
        ull inv6  = f2mul(t4, invsq2);
        ull inv12 = f2mul(inv6, inv6);
        a6  = f2add(a6, inv6);
        a12 = f2add(a12, inv12);
        ull diff = f2fma(inv6, MINUS1, inv12);   // inv12 - inv6
        ull c2   = f2mul(diff, invsq2);
        fx2 = f2fma(c2, dx2, fx2);
        fy2 = f2fma(c2, dy2, fy2);
        fz2 = f2fma(c2, dz2, fz2);
    }
}

__global__ __launch_bounds__(TPB, 6) void lj_kernel(const float* __restrict__ pos,
                                                    float* __restrict__ out) {
    __shared__ ulonglong2 sxy[JPAIRS];
    __shared__ ull        szz[JPAIRS];
    __shared__ float      ered[8];

    const int bi    = blockIdx.x;
    const int b     = bi >> 5;         // / (CHUNKS*JSPLIT)
    const int chunk = (bi >> 3) & 3;
    const int jpart = bi & 7;
    const int tid   = threadIdx.x;
    const int lane  = tid & 31;
    const int warp  = tid >> 5;

    const float* __restrict__ p = pos + (size_t)b * NATOMS * 3;

    // own i-atom (issue LDGs early to overlap with tile staging)
    const int i  = chunk * TPB + tid;
    const float xi = p[3 * i + 0];
    const float yi = p[3 * i + 1];
    const float zi = p[3 * i + 2];

    // stage packed, negated j-tile: pair m -> atoms (2m, 2m+1) of this eighth
    if (tid < JPAIRS) {
        const int j0 = jpart * JTILE + 2 * tid;
        float x0 = p[3 * j0 + 0], y0 = p[3 * j0 + 1], z0 = p[3 * j0 + 2];
        float x1 = p[3 * j0 + 3], y1 = p[3 * j0 + 4], z1 = p[3 * j0 + 5];
        ulonglong2 v;
        v.x = f2pack(-x0, -x1);
        v.y = f2pack(-y0, -y1);
        sxy[tid] = v;
        szz[tid] = f2pack(-z0, -z1);
    }
    __syncthreads();

    const ull xi2 = f2pack(xi, xi);
    const ull yi2 = f2pack(yi, yi);
    const ull zi2 = f2pack(zi, zi);

    ull fx2 = 0, fy2 = 0, fz2 = 0, a6 = 0, a12 = 0;

    if ((jpart >> 1) == chunk) {
        const int ii = i - jpart * JTILE;            // in [0, JTILE) iff self present
        const bool in = (ii >= 0) && (ii < JTILE);
        const int m0 = (in && ((ii & 1) == 0)) ? (ii >> 1) : -1;
        const int m1 = (in && ((ii & 1) == 1)) ? (ii >> 1) : -1;
        pair_loop<true>(sxy, szz, xi2, yi2, zi2, m0, m1, fx2, fy2, fz2, a6, a12);
    } else {
        pair_loop<false>(sxy, szz, xi2, yi2, zi2, -1, -1, fx2, fy2, fz2, a6, a12);
    }

    float fxl, fxh, fyl, fyh, fzl, fzh, a6l, a6h, a12l, a12h;
    f2unpack(fx2, fxl, fxh);
    f2unpack(fy2, fyl, fyh);
    f2unpack(fz2, fzl, fzh);
    f2unpack(a6, a6l, a6h);
    f2unpack(a12, a12l, a12h);

    float e  = 0.5f * ((a12l + a12h) - 2.0f * (a6l + a6h));
    float fx = 12.0f * (fxl + fxh);
    float fy = 12.0f * (fyl + fyh);
    float fz = 12.0f * (fzl + fzh);

    // oscillator term (mean precomputed by lj_pre): only jpart==0 blocks, once per i
    if (jpart == 0) {
        const float4 mn = d_mean[b];
        const float xcx = xi - mn.x, xcy = yi - mn.y, xcz = zi - mn.z;
        e  += 0.125f * fmaf(xcx, xcx, fmaf(xcy, xcy, xcz * xcz));
        fx -= 0.25f * xcx;
        fy -= 0.25f * xcy;
        fz -= 0.25f * xcz;
    }

    // partial forces into zero-initialized output (REDG, spread addresses)
    float* __restrict__ f = out + NBATCH + (size_t)(b * NATOMS + i) * 3;
    atomicAdd(f + 0, fx);
    atomicAdd(f + 1, fy);
    atomicAdd(f + 2, fz);

    // energy partial: warp shuffles -> shared -> one atomicAdd per block
    #pragma unroll
    for (int o = 16; o > 0; o >>= 1)
        e += __shfl_xor_sync(0xFFFFFFFFu, e, o);
    if (lane == 0) ered[warp] = e;
    __syncthreads();
    if (tid == 0) {
        float esum = 0.0f;
        #pragma unroll
        for (int k = 0; k < 8; k++) esum += ered[k];
        atomicAdd(out + b, esum);
    }
}

extern "C" void kernel_launch(void* const* d_in, const int* in_sizes, int n_in,
                              void* d_out, int out_size) {
    const float* pos = (const float*)d_in[0];
    float* out = (float*)d_out;
    lj_pre<<<NBATCH, TPB>>>(pos, out, out_size);
    lj_kernel<<<NBATCH * CHUNKS * JSPLIT, TPB>>>(pos, out);
}

// round 7
// speedup vs baseline: 1.0417x; 1.0417x over previous
#include <cuda_runtime.h>

#define NATOMS  1024
#define NBATCH  32
#define NTILE   8
#define TILE    128
#define TPAIRS  64            // packed j-pairs per tile
#define NPB     36            // tile-pairs per batch: 8 diag + 28 off-diag
#define THREADS 128
// grid = NBATCH * NPB = 1152 blocks

typedef unsigned long long ull;

__device__ __forceinline__ ull f2pack(float lo, float hi) {
    ull r;
    asm("mov.b64 %0, {%1, %2};" : "=l"(r)
        : "r"(__float_as_uint(lo)), "r"(__float_as_uint(hi)));
    return r;
}
__device__ __forceinline__ void f2unpack(ull v, float& lo, float& hi) {
    unsigned a, b;
    asm("mov.b64 {%0, %1}, %2;" : "=r"(a), "=r"(b) : "l"(v));
    lo = __uint_as_float(a);
    hi = __uint_as_float(b);
}
__device__ __forceinline__ ull f2add(ull a, ull b) {
    ull r; asm("add.rn.f32x2 %0, %1, %2;" : "=l"(r) : "l"(a), "l"(b)); return r;
}
__device__ __forceinline__ ull f2mul(ull a, ull b) {
    ull r; asm("mul.rn.f32x2 %0, %1, %2;" : "=l"(r) : "l"(a), "l"(b)); return r;
}
__device__ __forceinline__ ull f2fma(ull a, ull b, ull c) {
    ull r; asm("fma.rn.f32x2 %0, %1, %2, %3;" : "=l"(r) : "l"(a), "l"(b), "l"(c)); return r;
}

__global__ __launch_bounds__(THREADS, 8) void lj_kernel(const float* __restrict__ pos,
                                                        float* __restrict__ out) {
    __shared__ ulonglong2 sxy[TPAIRS];     // packed negated j-tile (-x0,-x1),(-y0,-y1)
    __shared__ ull        szz[TPAIRS];     // (-z0,-z1)
    __shared__ ull        fjx[4 * TPAIRS]; // per-warp j-force accumulators (packed)
    __shared__ ull        fjy[4 * TPAIRS];
    __shared__ ull        fjz[4 * TPAIRS];
    __shared__ float      wred[4 * 3];
    __shared__ float      ered[4];
    __shared__ float      smean[3];

    const int bi  = blockIdx.x;
    const int b   = bi / NPB;
    int rem = bi - b * NPB;                // tile-pair rank 0..35
    int ta = 0;
    while (rem >= NTILE - ta) { rem -= NTILE - ta; ta++; }
    const int tb = ta + rem;               // ta <= tb
    const bool diag = (ta == tb);

    const int tid  = threadIdx.x;
    const int lane = tid & 31;
    const int warp = tid >> 5;

    const float* __restrict__ p = pos + (size_t)b * NATOMS * 3;

    // own i-atom
    const int i  = ta * TILE + tid;
    const float xi = p[3 * i + 0];
    const float yi = p[3 * i + 1];
    const float zi = p[3 * i + 2];

    // stage packed, negated j-tile (tile tb): pair m -> atoms (2m, 2m+1)
    if (tid < TPAIRS) {
        const int j0 = tb * TILE + 2 * tid;
        float x0 = p[3 * j0 + 0], y0 = p[3 * j0 + 1], z0 = p[3 * j0 + 2];
        float x1 = p[3 * j0 + 3], y1 = p[3 * j0 + 4], z1 = p[3 * j0 + 5];
        ulonglong2 v;
        v.x = f2pack(-x0, -x1);
        v.y = f2pack(-y0, -y1);
        sxy[tid] = v;
        szz[tid] = f2pack(-z0, -z1);
    }
    // zero per-warp j-force accumulators
    for (int k = tid; k < 4 * TPAIRS; k += THREADS) {
        fjx[k] = 0; fjy[k] = 0; fjz[k] = 0;
    }

    // diag blocks also compute the batch mean (needed for oscillator)
    float mx = 0.0f, my = 0.0f, mz = 0.0f;
    if (diag) {
        for (int a = tid; a < NATOMS; a += THREADS) {
            mx += p[3 * a + 0];
            my += p[3 * a + 1];
            mz += p[3 * a + 2];
        }
        #pragma unroll
        for (int o = 16; o > 0; o >>= 1) {
            mx += __shfl_xor_sync(0xFFFFFFFFu, mx, o);
            my += __shfl_xor_sync(0xFFFFFFFFu, my, o);
            mz += __shfl_xor_sync(0xFFFFFFFFu, mz, o);
        }
        if (lane == 0) {
            wred[warp * 3 + 0] = mx;
            wred[warp * 3 + 1] = my;
            wred[warp * 3 + 2] = mz;
        }
    }
    __syncthreads();
    if (diag && tid == 0) {
        float sx = 0.0f, sy = 0.0f, sz = 0.0f;
        #pragma unroll
        for (int k = 0; k < 4; k++) {
            sx += wred[k * 3 + 0];
            sy += wred[k * 3 + 1];
            sz += wred[k * 3 + 2];
        }
        const float inv_n = 1.0f / (float)NATOMS;
        smean[0] = sx * inv_n; smean[1] = sy * inv_n; smean[2] = sz * inv_n;
    }
    if (diag) __syncthreads();

    const ull xi2 = f2pack(xi, xi);
    const ull yi2 = f2pack(yi, yi);
    const ull zi2 = f2pack(zi, zi);
    const ull MINUS1 = f2pack(-1.0f, -1.0f);

    ull fx2 = 0, fy2 = 0, fz2 = 0, a6 = 0, a12 = 0;

    if (diag) {
        // self-tile: full directed loop with self-pair masking; energy halved later
        const int ms = tid >> 1;
        const int m0 = ((tid & 1) == 0) ? ms : -1;
        const int m1 = ((tid & 1) == 1) ? ms : -1;
        #pragma unroll 8
        for (int m = 0; m < TPAIRS; m++) {
            ulonglong2 q = sxy[m];
            ull nz2 = szz[m];
            ull dx2 = f2add(xi2, q.x);
            ull dy2 = f2add(yi2, q.y);
            ull dz2 = f2add(zi2, nz2);
            ull sq2 = f2mul(dx2, dx2);
            sq2 = f2fma(dy2, dy2, sq2);
            sq2 = f2fma(dz2, dz2, sq2);
            float s0, s1;
            f2unpack(sq2, s0, s1);
            s0 = (m == m0) ? 3.0e38f : s0;      // self -> rcp underflows to 0
            s1 = (m == m1) ? 3.0e38f : s1;
            float r0 = __fdividef(1.0f, s0);
            float r1 = __fdividef(1.0f, s1);
            ull invsq2 = f2pack(r0, r1);
            ull t4    = f2mul(invsq2, invsq2);
            ull inv6  = f2mul(t4, invsq2);
            ull inv12 = f2mul(inv6, inv6);
            a6  = f2add(a6, inv6);
            a12 = f2add(a12, inv12);
            ull diff = f2fma(inv6, MINUS1, inv12);
            ull c2   = f2mul(diff, invsq2);
            fx2 = f2fma(c2, dx2, fx2);
            fy2 = f2fma(c2, dy2, fy2);
            fz2 = f2fma(c2, dz2, fz2);
        }
    } else {
        // cross-tile: each pair once; accumulate j-forces in this warp's shared copy.
        // Rotation p=(m+lane)&63 keeps lanes on distinct pairs every iteration.
        volatile ull* vfx = fjx + warp * TPAIRS;
        volatile ull* vfy = fjy + warp * TPAIRS;
        volatile ull* vfz = fjz + warp * TPAIRS;
        #pragma unroll 4
        for (int m = 0; m < TPAIRS; m++) {
            const int pp = (m + lane) & (TPAIRS - 1);
            ulonglong2 q = sxy[pp];
            ull nz2 = szz[pp];
            ull dx2 = f2add(xi2, q.x);
            ull dy2 = f2add(yi2, q.y);
            ull dz2 = f2add(zi2, nz2);
            ull sq2 = f2mul(dx2, dx2);
            sq2 = f2fma(dy2, dy2, sq2);
            sq2 = f2fma(dz2, dz2, sq2);
            float s0, s1;
            f2unpack(sq2, s0, s1);
            float r0 = __fdividef(1.0f, s0);
            float r1 = __fdividef(1.0f, s1);
            ull invsq2 = f2pack(r0, r1);
            ull t4    = f2mul(invsq2, invsq2);
            ull inv6  = f2mul(t4, invsq2);
            ull inv12 = f2mul(inv6, inv6);
            a6  = f2add(a6, inv6);
            a12 = f2add(a12, inv12);
            ull diff = f2fma(inv6, MINUS1, inv12);
            ull c2   = f2mul(diff, invsq2);
            fx2 = f2fma(c2, dx2, fx2);
            fy2 = f2fma(c2, dy2, fy2);
            fz2 = f2fma(c2, dz2, fz2);
            // j-side accumulation (force on j = -12 * c2 * d; sign applied at end)
            vfx[pp] = f2fma(c2, dx2, vfx[pp]);
            vfy[pp] = f2fma(c2, dy2, vfy[pp]);
            vfz[pp] = f2fma(c2, dz2, vfz[pp]);
        }
    }

    float fxl, fxh, fyl, fyh, fzl, fzh, a6l, a6h, a12l, a12h;
    f2unpack(fx2, fxl, fxh);
    f2unpack(fy2, fyl, fyh);
    f2unpack(fz2, fzl, fzh);
    f2unpack(a6, a6l, a6h);
    f2unpack(a12, a12l, a12h);

    const float ew = diag ? 0.5f : 1.0f;   // diag counts each pair twice
    float e  = ew * ((a12l + a12h) - 2.0f * (a6l + a6h));
    float fx = 12.0f * (fxl + fxh);
    float fy = 12.0f * (fyl + fyh);
    float fz = 12.0f * (fzl + fzh);

    if (diag) {
        // oscillator: each i belongs to exactly one diag block
        const float xcx = xi - smean[0], xcy = yi - smean[1], xcz = zi - smean[2];
        e  += 0.125f * fmaf(xcx, xcx, fmaf(xcy, xcy, xcz * xcz));
        fx -= 0.25f * xcx;
        fy -= 0.25f * xcy;
        fz -= 0.25f * xcz;
    }

    // i-side forces
    float* __restrict__ f = out + NBATCH + (size_t)(b * NATOMS + i) * 3;
    atomicAdd(f + 0, fx);
    atomicAdd(f + 1, fy);
    atomicAdd(f + 2, fz);

    __syncthreads();

    // j-side forces (off-diag only): reduce the 4 warp copies, negate, scale
    if (!diag && tid < TPAIRS) {
        ull sx = 0, sy = 0, sz = 0;
        #pragma unroll
        for (int w = 0; w < 4; w++) {
            sx = f2add(sx, fjx[w * TPAIRS + tid]);
            sy = f2add(sy, fjy[w * TPAIRS + tid]);
            sz = f2add(sz, fjz[w * TPAIRS + tid]);
        }
        float sx0, sx1, sy0, sy1, sz0, sz1;
        f2unpack(sx, sx0, sx1);
        f2unpack(sy, sy0, sy1);
        f2unpack(sz, sz0, sz1);
        const int j0 = tb * TILE + 2 * tid;
        float* __restrict__ fj = out + NBATCH + (size_t)(b * NATOMS + j0) * 3;
        atomicAdd(fj + 0, -12.0f * sx0);
        atomicAdd(fj + 1, -12.0f * sy0);
        atomicAdd(fj + 2, -12.0f * sz0);
        atomicAdd(fj + 3, -12.0f * sx1);
        atomicAdd(fj + 4, -12.0f * sy1);
        atomicAdd(fj + 5, -12.0f * sz1);
    }

    // energy: warp shuffles -> shared -> one atomicAdd per block
    #pragma unroll
    for (int o = 16; o > 0; o >>= 1)
        e += __shfl_xor_sync(0xFFFFFFFFu, e, o);
    if (lane == 0) ered[warp] = e;
    __syncthreads();
    if (tid == 0) {
        float esum = ered[0] + ered[1] + ered[2] + ered[3];
        atomicAdd(out + b, esum);
    }
}

extern "C" void kernel_launch(void* const* d_in, const int* in_sizes, int n_in,
                              void* d_out, int out_size) {
    const float* pos = (const float*)d_in[0];
    float* out = (float*)d_out;
    cudaMemsetAsync(out, 0, (size_t)out_size * sizeof(float));
    lj_kernel<<<NBATCH * NPB, THREADS>>>(pos, out);
}

// round 8
// speedup vs baseline: 1.1779x; 1.1307x over previous
#include <cuda_runtime.h>

#define NATOMS  1024
#define NBATCH  32
#define NTILE   8
#define TILE    128
#define TPAIRS  64            // packed j-pairs per tile
#define NPB     36            // tile-pairs per batch: 8 diag + 28 off-diag
#define THREADS 64            // each thread owns TWO i-atoms (tid, tid+64)
// grid = NBATCH * NPB = 1152 blocks of 64 threads

typedef unsigned long long ull;

__device__ __forceinline__ ull f2pack(float lo, float hi) {
    ull r;
    asm("mov.b64 %0, {%1, %2};" : "=l"(r)
        : "r"(__float_as_uint(lo)), "r"(__float_as_uint(hi)));
    return r;
}
__device__ __forceinline__ void f2unpack(ull v, float& lo, float& hi) {
    unsigned a, b;
    asm("mov.b64 {%0, %1}, %2;" : "=r"(a), "=r"(b) : "l"(v));
    lo = __uint_as_float(a);
    hi = __uint_as_float(b);
}
__device__ __forceinline__ ull f2add(ull a, ull b) {
    ull r; asm("add.rn.f32x2 %0, %1, %2;" : "=l"(r) : "l"(a), "l"(b)); return r;
}
__device__ __forceinline__ ull f2mul(ull a, ull b) {
    ull r; asm("mul.rn.f32x2 %0, %1, %2;" : "=l"(r) : "l"(a), "l"(b)); return r;
}
__device__ __forceinline__ ull f2fma(ull a, ull b, ull c) {
    ull r; asm("fma.rn.f32x2 %0, %1, %2, %3;" : "=l"(r) : "l"(a), "l"(b), "l"(c)); return r;
}

__global__ void lj_zero_out(float* __restrict__ out, int n) {
    int idx = blockIdx.x * blockDim.x + threadIdx.x;
    for (; idx < n; idx += gridDim.x * blockDim.x) out[idx] = 0.0f;
}

// LJ core for one packed i vs one packed j-pair. Returns c2; accumulates e/f.
__device__ __forceinline__ ull lj_core(
    ull xi2, ull yi2, ull zi2, ull nx2, ull ny2, ull nz2,
    int m, int m0, int m1, bool self_mask, ull MINUS1,
    ull& dx2o, ull& dy2o, ull& dz2o,
    ull& fx2, ull& fy2, ull& fz2, ull& a6, ull& a12)
{
    ull dx2 = f2add(xi2, nx2);
    ull dy2 = f2add(yi2, ny2);
    ull dz2 = f2add(zi2, nz2);
    ull sq2 = f2mul(dx2, dx2);
    sq2 = f2fma(dy2, dy2, sq2);
    sq2 = f2fma(dz2, dz2, sq2);
    float s0, s1;
    f2unpack(sq2, s0, s1);
    if (self_mask) {                    // self-pair -> rcp underflows to 0
        s0 = (m == m0) ? 3.0e38f : s0;
        s1 = (m == m1) ? 3.0e38f : s1;
    }
    float r0 = __fdividef(1.0f, s0);    // MUFU.RCP
    float r1 = __fdividef(1.0f, s1);
    ull invsq2 = f2pack(r0, r1);
    ull t4    = f2mul(invsq2, invsq2);
    ull inv6  = f2mul(t4, invsq2);
    ull inv12 = f2mul(inv6, inv6);
    a6  = f2add(a6, inv6);
    a12 = f2add(a12, inv12);
    ull diff = f2fma(inv6, MINUS1, inv12);
    ull c2   = f2mul(diff, invsq2);
    fx2 = f2fma(c2, dx2, fx2);
    fy2 = f2fma(c2, dy2, fy2);
    fz2 = f2fma(c2, dz2, fz2);
    dx2o = dx2; dy2o = dy2; dz2o = dz2;
    return c2;
}

__global__ __launch_bounds__(THREADS, 8) void lj_kernel(const float* __restrict__ pos,
                                                        float* __restrict__ out) {
    __shared__ ulonglong2 sxy[TPAIRS];     // packed negated j-tile (-x0,-x1),(-y0,-y1)
    __shared__ ull        szz[TPAIRS];     // (-z0,-z1)
    __shared__ ull        fjx[2 * TPAIRS]; // per-warp j-force accumulators (packed)
    __shared__ ull        fjy[2 * TPAIRS];
    __shared__ ull        fjz[2 * TPAIRS];
    __shared__ float      wred[2 * 3];
    __shared__ float      ered[2];
    __shared__ float      smean[3];

    const int bi  = blockIdx.x;
    const int b   = bi / NPB;
    int rem = bi - b * NPB;                // tile-pair rank 0..35
    int ta = 0;
    while (rem >= NTILE - ta) { rem -= NTILE - ta; ta++; }
    const int tb = ta + rem;               // ta <= tb
    const bool diag = (ta == tb);

    const int tid  = threadIdx.x;
    const int lane = tid & 31;
    const int warp = tid >> 5;

    const float* __restrict__ p = pos + (size_t)b * NATOMS * 3;

    // two owned i-atoms
    const int i0 = ta * TILE + tid;
    const int i1 = i0 + THREADS;
    const float xa = p[3 * i0 + 0], ya = p[3 * i0 + 1], za = p[3 * i0 + 2];
    const float xb = p[3 * i1 + 0], yb = p[3 * i1 + 1], zb = p[3 * i1 + 2];

    // stage packed, negated j-tile (tile tb): pair m -> atoms (2m, 2m+1)
    {
        const int j0 = tb * TILE + 2 * tid;
        float x0 = p[3 * j0 + 0], y0 = p[3 * j0 + 1], z0 = p[3 * j0 + 2];
        float x1 = p[3 * j0 + 3], y1 = p[3 * j0 + 4], z1 = p[3 * j0 + 5];
        ulonglong2 v;
        v.x = f2pack(-x0, -x1);
        v.y = f2pack(-y0, -y1);
        sxy[tid] = v;
        szz[tid] = f2pack(-z0, -z1);
    }
    // zero per-warp j-force accumulators (2 warps x 64 pairs)
    #pragma unroll
    for (int k = 0; k < 2; k++) {
        fjx[k * THREADS + tid] = 0;
        fjy[k * THREADS + tid] = 0;
        fjz[k * THREADS + tid] = 0;
    }

    // diag blocks compute batch mean (for oscillator)
    if (diag) {
        float mx = 0.0f, my = 0.0f, mz = 0.0f;
        for (int a = tid; a < NATOMS; a += THREADS) {
            mx += p[3 * a + 0];
            my += p[3 * a + 1];
            mz += p[3 * a + 2];
        }
        #pragma unroll
        for (int o = 16; o > 0; o >>= 1) {
            mx += __shfl_xor_sync(0xFFFFFFFFu, mx, o);
            my += __shfl_xor_sync(0xFFFFFFFFu, my, o);
            mz += __shfl_xor_sync(0xFFFFFFFFu, mz, o);
        }
        if (lane == 0) {
            wred[warp * 3 + 0] = mx;
            wred[warp * 3 + 1] = my;
            wred[warp * 3 + 2] = mz;
        }
    }
    __syncthreads();
    if (diag && tid == 0) {
        const float inv_n = 1.0f / (float)NATOMS;
        smean[0] = (wred[0] + wred[3]) * inv_n;
        smean[1] = (wred[1] + wred[4]) * inv_n;
        smean[2] = (wred[2] + wred[5]) * inv_n;
    }
    if (diag) __syncthreads();

    const ull xa2 = f2pack(xa, xa), ya2 = f2pack(ya, ya), za2 = f2pack(za, za);
    const ull xb2 = f2pack(xb, xb), yb2 = f2pack(yb, yb), zb2 = f2pack(zb, zb);
    const ull MINUS1 = f2pack(-1.0f, -1.0f);

    ull fxa = 0, fya = 0, fza = 0, a6a = 0, a12a = 0;
    ull fxb = 0, fyb = 0, fzb = 0, a6b = 0, a12b = 0;

    if (diag) {
        // self-tile: full directed loop with self-pair masks; no j-side accumulation
        const int slot = tid & 1;
        const int m0a = (slot == 0) ? (tid >> 1) : -1;
        const int m1a = (slot == 1) ? (tid >> 1) : -1;
        const int m0b = (slot == 0) ? (32 + (tid >> 1)) : -1;
        const int m1b = (slot == 1) ? (32 + (tid >> 1)) : -1;
        ull d0, d1, d2;
        #pragma unroll 4
        for (int m = 0; m < TPAIRS; m++) {
            ulonglong2 q = sxy[m];
            ull nz2 = szz[m];
            lj_core(xa2, ya2, za2, q.x, q.y, nz2, m, m0a, m1a, true, MINUS1,
                    d0, d1, d2, fxa, fya, fza, a6a, a12a);
            lj_core(xb2, yb2, zb2, q.x, q.y, nz2, m, m0b, m1b, true, MINUS1,
                    d0, d1, d2, fxb, fyb, fzb, a6b, a12b);
        }
    } else {
        // cross-tile: each pair once; per-warp shared j-accumulators, one RMW per iter
        volatile ull* vfx = fjx + warp * TPAIRS;
        volatile ull* vfy = fjy + warp * TPAIRS;
        volatile ull* vfz = fjz + warp * TPAIRS;
        ull dxa, dya, dza, dxb, dyb, dzb;
        #pragma unroll 4
        for (int m = 0; m < TPAIRS; m++) {
            const int pp = (m + lane) & (TPAIRS - 1);   // lanes on distinct pairs
            ulonglong2 q = sxy[pp];
            ull nz2 = szz[pp];
            ull ca = lj_core(xa2, ya2, za2, q.x, q.y, nz2, 0, -1, -1, false, MINUS1,
                             dxa, dya, dza, fxa, fya, fza, a6a, a12a);
            ull cb = lj_core(xb2, yb2, zb2, q.x, q.y, nz2, 0, -1, -1, false, MINUS1,
                             dxb, dyb, dzb, fxb, fyb, fzb, a6b, a12b);
            // combined j-side RMW: vf += ca*da + cb*db  (one load/store per component)
            vfx[pp] = f2fma(cb, dxb, f2fma(ca, dxa, vfx[pp]));
            vfy[pp] = f2fma(cb, dyb, f2fma(ca, dya, vfy[pp]));
            vfz[pp] = f2fma(cb, dzb, f2fma(ca, dza, vfz[pp]));
        }
    }

    const float ew = diag ? 0.5f : 1.0f;
    float e;
    {
        float l0, h0, l1, h1;
        f2unpack(a12a, l0, h0); f2unpack(a6a, l1, h1);
        e = ew * ((l0 + h0) - 2.0f * (l1 + h1));
        f2unpack(a12b, l0, h0); f2unpack(a6b, l1, h1);
        e += ew * ((l0 + h0) - 2.0f * (l1 + h1));
    }

    float fax, fay, faz, fbx, fby, fbz;
    {
        float lo, hi;
        f2unpack(fxa, lo, hi); fax = 12.0f * (lo + hi);
        f2unpack(fya, lo, hi); fay = 12.0f * (lo + hi);
        f2unpack(fza, lo, hi); faz = 12.0f * (lo + hi);
        f2unpack(fxb, lo, hi); fbx = 12.0f * (lo + hi);
        f2unpack(fyb, lo, hi); fby = 12.0f * (lo + hi);
        f2unpack(fzb, lo, hi); fbz = 12.0f * (lo + hi);
    }

    if (diag) {
        // oscillator: each i belongs to exactly one diag block
        float xc = xa - smean[0], yc = ya - smean[1], zc = za - smean[2];
        e  += 0.125f * fmaf(xc, xc, fmaf(yc, yc, zc * zc));
        fax -= 0.25f * xc; fay -= 0.25f * yc; faz -= 0.25f * zc;
        xc = xb - smean[0]; yc = yb - smean[1]; zc = zb - smean[2];
        e  += 0.125f * fmaf(xc, xc, fmaf(yc, yc, zc * zc));
        fbx -= 0.25f * xc; fby -= 0.25f * yc; fbz -= 0.25f * zc;
    }

    // i-side forces
    float* __restrict__ fA = out + NBATCH + (size_t)(b * NATOMS + i0) * 3;
    atomicAdd(fA + 0, fax);
    atomicAdd(fA + 1, fay);
    atomicAdd(fA + 2, faz);
    float* __restrict__ fB = out + NBATCH + (size_t)(b * NATOMS + i1) * 3;
    atomicAdd(fB + 0, fbx);
    atomicAdd(fB + 1, fby);
    atomicAdd(fB + 2, fbz);

    __syncthreads();

    // j-side forces (off-diag only): reduce the 2 warp copies, negate, scale
    if (!diag) {
        ull sx = f2add(fjx[tid], fjx[TPAIRS + tid]);
        ull sy = f2add(fjy[tid], fjy[TPAIRS + tid]);
        ull sz = f2add(fjz[tid], fjz[TPAIRS + tid]);
        float sx0, sx1, sy0, sy1, sz0, sz1;
        f2unpack(sx, sx0, sx1);
        f2unpack(sy, sy0, sy1);
        f2unpack(sz, sz0, sz1);
        const int j0 = tb * TILE + 2 * tid;
        float* __restrict__ fj = out + NBATCH + (size_t)(b * NATOMS + j0) * 3;
        atomicAdd(fj + 0, -12.0f * sx0);
        atomicAdd(fj + 1, -12.0f * sy0);
        atomicAdd(fj + 2, -12.0f * sz0);
        atomicAdd(fj + 3, -12.0f * sx1);
        atomicAdd(fj + 4, -12.0f * sy1);
        atomicAdd(fj + 5, -12.0f * sz1);
    }

    // energy: warp shuffles -> shared -> one atomicAdd per block
    #pragma unroll
    for (int o = 16; o > 0; o >>= 1)
        e += __shfl_xor_sync(0xFFFFFFFFu, e, o);
    if (lane == 0) ered[warp] = e;
    __syncthreads();
    if (tid == 0) atomicAdd(out + b, ered[0] + ered[1]);
}

extern "C" void kernel_launch(void* const* d_in, const int* in_sizes, int n_in,
                              void* d_out, int out_size) {
    const float* pos = (const float*)d_in[0];
    float* out = (float*)d_out;
    lj_zero_out<<<148, 256>>>(out, out_size);
    lj_kernel<<<NBATCH * NPB, THREADS>>>(pos, out);
}